// round 1
// baseline (speedup 1.0000x reference)
#include <cuda_runtime.h>
#include <math.h>

#define R 256
#define F4 32          // 128 features = 32 float4

// Scratch (static device arrays -- allowed; no runtime allocation)
__device__ float4 g_G[R * R * F4];     // combined weighted grid
__device__ float4 g_tmp[R * R * F4];   // blur pass-1 intermediate
__device__ float  g_kern[64];          // packed gaussian kernels, offset = s-2

// ---------------------------------------------------------------------------
// Gaussian kernels (double precision, matches scipy.signal.gaussian + norm)
// ---------------------------------------------------------------------------
__global__ void k_init_kern() {
    int l = threadIdx.x;
    if (l < 1 || l > 5) return;
    int s = 1 << l;
    int off = s - 2;
    double stdv = s * 0.5;
    double w[32];
    double sum = 0.0;
    for (int n = 0; n < s; n++) {
        double x = ((double)n - (s - 1) * 0.5) / stdv;
        w[n] = exp(-0.5 * x * x);
        sum += w[n];
    }
    for (int n = 0; n < s; n++) g_kern[off + n] = (float)(w[n] / sum);
}

// G = b_levels[0] * base
__global__ void k_initG(const float4* __restrict__ base,
                        const float* __restrict__ b_levels) {
    int idx = blockIdx.x * blockDim.x + threadIdx.x;
    float b0 = b_levels[0];
    float4 v = base[idx];
    g_G[idx] = make_float4(b0 * v.x, b0 * v.y, b0 * v.z, b0 * v.w);
}

__device__ __forceinline__ int reflect_i(int c) {
    c = (c < 0) ? -c : c;
    return (c > R - 1) ? (2 * (R - 1) - c) : c;
}

// ---------------------------------------------------------------------------
// Separable blur, axis 0 (rows). base -> g_tmp
// y[i] = sum_j kern[j] * x[reflect(i + j - S/2)]
// Block: one column j, 64-row tile. Sliding-window register accumulation.
// ---------------------------------------------------------------------------
template <int S>
__global__ void __launch_bounds__(256) k_blur0(const float4* __restrict__ in) {
    __shared__ float4 sh[64 + S][F4];
    int j  = blockIdx.x;
    int i0 = blockIdx.y * 64;
    int t  = threadIdx.x;
    int f4 = t & 31, tg = t >> 5;

    float kr[S];
#pragma unroll
    for (int n = 0; n < S; n++) kr[n] = g_kern[S - 2 + n];

    for (int rr = tg; rr < 64 + S; rr += 8) {
        int c = reflect_i(i0 - S / 2 + rr);
        sh[rr][f4] = in[(c * R + j) * F4 + f4];
    }
    __syncthreads();

    float4 acc[8];
#pragma unroll
    for (int q = 0; q < 8; q++) acc[q] = make_float4(0.f, 0.f, 0.f, 0.f);
    int base = tg * 8;
#pragma unroll
    for (int r = 0; r < 8 + S - 1; r++) {
        float4 v = sh[base + r][f4];
#pragma unroll
        for (int q = 0; q < 8; q++) {
            int jj = r - q;
            if (jj >= 0 && jj < S) {
                float k = kr[jj];
                acc[q].x += k * v.x; acc[q].y += k * v.y;
                acc[q].z += k * v.z; acc[q].w += k * v.w;
            }
        }
    }
#pragma unroll
    for (int q = 0; q < 8; q++)
        g_tmp[((i0 + base + q) * R + j) * F4 + f4] = acc[q];
}

// ---------------------------------------------------------------------------
// Separable blur, axis 1 (cols) + weighted accumulate into G.
// ---------------------------------------------------------------------------
template <int S>
__global__ void __launch_bounds__(256) k_blur1_acc(const float* __restrict__ b_levels,
                                                   int lvl) {
    __shared__ float4 sh[64 + S][F4];
    int i  = blockIdx.x;
    int j0 = blockIdx.y * 64;
    int t  = threadIdx.x;
    int f4 = t & 31, tg = t >> 5;

    float kr[S];
#pragma unroll
    for (int n = 0; n < S; n++) kr[n] = g_kern[S - 2 + n];

    for (int rr = tg; rr < 64 + S; rr += 8) {
        int c = reflect_i(j0 - S / 2 + rr);
        sh[rr][f4] = g_tmp[(i * R + c) * F4 + f4];
    }
    __syncthreads();

    float4 acc[8];
#pragma unroll
    for (int q = 0; q < 8; q++) acc[q] = make_float4(0.f, 0.f, 0.f, 0.f);
    int base = tg * 8;
#pragma unroll
    for (int r = 0; r < 8 + S - 1; r++) {
        float4 v = sh[base + r][f4];
#pragma unroll
        for (int q = 0; q < 8; q++) {
            int jj = r - q;
            if (jj >= 0 && jj < S) {
                float k = kr[jj];
                acc[q].x += k * v.x; acc[q].y += k * v.y;
                acc[q].z += k * v.z; acc[q].w += k * v.w;
            }
        }
    }
    float b = b_levels[lvl];
#pragma unroll
    for (int q = 0; q < 8; q++) {
        int o = (i * R + (j0 + base + q)) * F4 + f4;
        float4 g = g_G[o];
        g.x += b * acc[q].x; g.y += b * acc[q].y;
        g.z += b * acc[q].z; g.w += b * acc[q].w;
        g_G[o] = g;
    }
}

// ---------------------------------------------------------------------------
// Points: bilinear gather from G + MLP (128x128 relu + 128x4), fused.
// 128 points per block, 256 threads.
// Shared layout (bytes):
//   fused4 : 128*33 float4            = 67584
//   w1t4   : 128*33 float4 (W1^T)     = 67584
//   offs   : 4*128 int                =  2048
//   wts    : 4*128 float              =  2048
//   b1s    : 128 float                =   512
//   w2s    : 512 float                =  2048
//   part   : 4*8*128 float            = 16384
// total = 158208
// ---------------------------------------------------------------------------
#define SMEM_PTS 158208

__global__ void __launch_bounds__(256, 1) k_points(
    const float* __restrict__ pt,
    const float* __restrict__ W1,
    const float* __restrict__ b1,
    const float* __restrict__ W2,
    const float* __restrict__ b2,
    float* __restrict__ out)
{
    extern __shared__ unsigned char smem_raw[];
    float4* fused4 = (float4*)smem_raw;
    float4* w1t4   = (float4*)(smem_raw + 67584);
    int*    offs   = (int*)  (smem_raw + 135168);
    float*  wts    = (float*)(smem_raw + 137216);
    float*  b1s    = (float*)(smem_raw + 139264);
    float*  w2s    = (float*)(smem_raw + 139776);
    float*  part   = (float*)(smem_raw + 141824);

    int t   = threadIdx.x;
    int blk = blockIdx.x;

    // --- W1 transpose into shared: w1t4[k][f4] (row stride 33 float4) ---
#pragma unroll
    for (int it = 0; it < 16; it++) {
        int task = it * 256 + t;
        int f4 = task >> 7;
        int k  = task & 127;
        float v0 = W1[(4 * f4 + 0) * 128 + k];
        float v1 = W1[(4 * f4 + 1) * 128 + k];
        float v2 = W1[(4 * f4 + 2) * 128 + k];
        float v3 = W1[(4 * f4 + 3) * 128 + k];
        w1t4[k * 33 + f4] = make_float4(v0, v1, v2, v3);
    }
    if (t < 128) b1s[t] = b1[t];
    w2s[t] = W2[t];
    w2s[256 + t] = W2[256 + t];

    // --- per-point indices/weights ---
    if (t < 128) {
        int pg = blk * 128 + t;
        float px = pt[2 * pg];
        float py = pt[2 * pg + 1];
        float ax = (px + 1.0f) / 2.0f * 255.0f;   // same fp32 ops as reference
        float ay = (py + 1.0f) / 2.0f * 255.0f;
        int ix = (int)ax; if (ix > 255) ix = 255;
        int iy = (int)ay; if (iy > 255) iy = 255;
        float fx = ax - (float)ix;
        float fy = ay - (float)iy;
        int ix1 = (ix + 1 > 255) ? 255 : ix + 1;
        int iy1 = (iy + 1 > 255) ? 255 : iy + 1;
        offs[t]       = (ix  * 256 + iy ) * 32;
        offs[128 + t] = (ix  * 256 + iy1) * 32;
        offs[256 + t] = (ix1 * 256 + iy ) * 32;
        offs[384 + t] = (ix1 * 256 + iy1) * 32;
        wts[t]        = (1.0f - fx) * (1.0f - fy);
        wts[128 + t]  = (1.0f - fx) * fy;
        wts[256 + t]  = fx * (1.0f - fy);
        wts[384 + t]  = fx * fy;
    }
    __syncthreads();

    // --- gather: warp = one point, lanes = 32 float4 features (coalesced) ---
#pragma unroll
    for (int it = 0; it < 16; it++) {
        int task = it * 256 + t;
        int p  = task >> 5;
        int f4 = task & 31;
        float w00 = wts[p], w01 = wts[128 + p], w10 = wts[256 + p], w11 = wts[384 + p];
        float4 c00 = g_G[offs[p]       + f4];
        float4 c01 = g_G[offs[128 + p] + f4];
        float4 c10 = g_G[offs[256 + p] + f4];
        float4 c11 = g_G[offs[384 + p] + f4];
        float4 v;
        v.x = w00 * c00.x + w01 * c01.x + w10 * c10.x + w11 * c11.x;
        v.y = w00 * c00.y + w01 * c01.y + w10 * c10.y + w11 * c11.y;
        v.z = w00 * c00.z + w01 * c01.z + w10 * c10.z + w11 * c11.z;
        v.w = w00 * c00.w + w01 * c01.w + w10 * c10.w + w11 * c11.w;
        fused4[p * 33 + f4] = v;
    }
    __syncthreads();

    // --- GEMM: thread (li,lj) computes points {li+16q} x ks {lj+16r} ---
    int li = t & 15;
    int lj = t >> 4;
    float acc[8][8];
#pragma unroll
    for (int q = 0; q < 8; q++)
#pragma unroll
        for (int r = 0; r < 8; r++) acc[q][r] = 0.0f;

#pragma unroll 4
    for (int f4 = 0; f4 < 32; f4++) {
        float4 a[8], bb[8];
#pragma unroll
        for (int q = 0; q < 8; q++) a[q] = fused4[(li + 16 * q) * 33 + f4];
#pragma unroll
        for (int r = 0; r < 8; r++) bb[r] = w1t4[(lj + 16 * r) * 33 + f4];
#pragma unroll
        for (int q = 0; q < 8; q++)
#pragma unroll
            for (int r = 0; r < 8; r++) {
                acc[q][r] += a[q].x * bb[r].x;
                acc[q][r] += a[q].y * bb[r].y;
                acc[q][r] += a[q].z * bb[r].z;
                acc[q][r] += a[q].w * bb[r].w;
            }
    }

    // --- bias + relu + W2 partials ---
    float po[8][4];
#pragma unroll
    for (int q = 0; q < 8; q++)
#pragma unroll
        for (int o = 0; o < 4; o++) po[q][o] = 0.0f;

#pragma unroll
    for (int r = 0; r < 8; r++) {
        int k = lj + 16 * r;
        float bias = b1s[k];
        float w0 = w2s[k * 4 + 0], w1v = w2s[k * 4 + 1];
        float w2v = w2s[k * 4 + 2], w3 = w2s[k * 4 + 3];
#pragma unroll
        for (int q = 0; q < 8; q++) {
            float h = acc[q][r] + bias;
            h = fmaxf(h, 0.0f);
            po[q][0] += h * w0;  po[q][1] += h * w1v;
            po[q][2] += h * w2v; po[q][3] += h * w3;
        }
    }

    // reduce the two j's within each warp (lanes t and t^16 share li)
#pragma unroll
    for (int q = 0; q < 8; q++)
#pragma unroll
        for (int o = 0; o < 4; o++)
            po[q][o] += __shfl_xor_sync(0xffffffffu, po[q][o], 16);

    if ((t & 16) == 0) {
        int w = t >> 5;
#pragma unroll
        for (int q = 0; q < 8; q++) {
            int p = li + 16 * q;
#pragma unroll
            for (int o = 0; o < 4; o++)
                part[(o * 8 + w) * 128 + p] = po[q][o];   // conflict-free STS
        }
    }
    __syncthreads();

    // --- final cross-warp reduce + bias2 + store ---
#pragma unroll
    for (int it = 0; it < 2; it++) {
        int task = it * 256 + t;
        int p = task >> 2;
        int o = task & 3;
        float s = b2[o];
#pragma unroll
        for (int w = 0; w < 8; w++) s += part[(o * 8 + w) * 128 + p];
        out[(blk * 128 + p) * 4 + o] = s;
    }
}

// ---------------------------------------------------------------------------
extern "C" void kernel_launch(void* const* d_in, const int* in_sizes, int n_in,
                              void* d_out, int out_size) {
    const float* pt       = (const float*)d_in[0];
    const float4* base4   = (const float4*)d_in[1];
    const float* b_levels = (const float*)d_in[2];
    const float* W1       = (const float*)d_in[3];
    const float* b1       = (const float*)d_in[4];
    const float* W2       = (const float*)d_in[5];
    const float* b2       = (const float*)d_in[6];
    float* out            = (float*)d_out;

    cudaFuncSetAttribute(k_points, cudaFuncAttributeMaxDynamicSharedMemorySize,
                         SMEM_PTS);

    k_init_kern<<<1, 32>>>();
    k_initG<<<4096, 512>>>(base4, b_levels);

    dim3 bgrid(256, 4);
    // level 1..5, s = 2,4,8,16,32
    k_blur0<2><<<bgrid, 256>>>(base4);
    k_blur1_acc<2><<<bgrid, 256>>>(b_levels, 1);
    k_blur0<4><<<bgrid, 256>>>(base4);
    k_blur1_acc<4><<<bgrid, 256>>>(b_levels, 2);
    k_blur0<8><<<bgrid, 256>>>(base4);
    k_blur1_acc<8><<<bgrid, 256>>>(b_levels, 3);
    k_blur0<16><<<bgrid, 256>>>(base4);
    k_blur1_acc<16><<<bgrid, 256>>>(b_levels, 4);
    k_blur0<32><<<bgrid, 256>>>(base4);
    k_blur1_acc<32><<<bgrid, 256>>>(b_levels, 5);

    k_points<<<2048, 256, SMEM_PTS>>>(pt, W1, b1, W2, b2, out);
}

// round 2
// speedup vs baseline: 1.6654x; 1.6654x over previous
#include <cuda_runtime.h>
#include <math.h>

#define R 256
#define F4 32           // 128 features = 32 float4
#define NPIX (R * R)

// Static device scratch (no runtime allocation)
__device__ float4 g_G[NPIX * F4];        // combined weighted grid   (33.5 MB)
__device__ float4 g_H[NPIX * F4];        // H = G @ W1 + b1          (33.5 MB)
__device__ float4 g_tmp[5 * NPIX * F4];  // row-blurred levels 1..5  (168 MB)

// Gaussian kernel weights, computed on host in double, passed by value.
// offset for window s is (s-2): s=2 @0, 4 @2, 8 @6, 16 @14, 32 @30..61
struct KW { float w[62]; };

__device__ __forceinline__ int reflect_i(int c) {
    c = (c < 0) ? -c : c;
    return (c > R - 1) ? (2 * (R - 1) - c) : c;
}

// ---------------------------------------------------------------------------
// Row pass, ALL levels fused: load 96-row tile once, emit 5 blurred levels.
// y[i] = sum_{jj=0..S-1} k[jj] * x[reflect(i + jj - S/2)]
// ---------------------------------------------------------------------------
template <int S>
__device__ __forceinline__ void row_level(const float4 (*sh)[F4], const KW& kw,
                                          int base, int f4, int lvl, int i0, int j)
{
    float4 acc[8];
#pragma unroll
    for (int q = 0; q < 8; q++) acc[q] = make_float4(0.f, 0.f, 0.f, 0.f);
#pragma unroll
    for (int r = 0; r < 8 + S - 1; r++) {
        float4 v = sh[base + 16 - S / 2 + r][f4];
#pragma unroll
        for (int q = 0; q < 8; q++) {
            int jj = r - q;
            if (jj >= 0 && jj < S) {
                float k = kw.w[S - 2 + jj];
                acc[q].x += k * v.x; acc[q].y += k * v.y;
                acc[q].z += k * v.z; acc[q].w += k * v.w;
            }
        }
    }
    size_t lb = (size_t)lvl * NPIX * F4;
#pragma unroll
    for (int q = 0; q < 8; q++)
        g_tmp[lb + ((size_t)(i0 + base + q) * R + j) * F4 + f4] = acc[q];
}

__global__ void __launch_bounds__(256) k_rows(const float4* __restrict__ in, KW kw)
{
    __shared__ float4 sh[96][F4];
    int j  = blockIdx.x;
    int i0 = blockIdx.y * 64;
    int t  = threadIdx.x;
    int f4 = t & 31, tg = t >> 5;

    for (int rr = tg; rr < 96; rr += 8) {
        int c = reflect_i(i0 - 16 + rr);
        sh[rr][f4] = in[((size_t)c * R + j) * F4 + f4];
    }
    __syncthreads();

    int base = tg * 8;
    row_level<2 >(sh, kw, base, f4, 0, i0, j);
    row_level<4 >(sh, kw, base, f4, 1, i0, j);
    row_level<8 >(sh, kw, base, f4, 2, i0, j);
    row_level<16>(sh, kw, base, f4, 3, i0, j);
    row_level<32>(sh, kw, base, f4, 4, i0, j);
}

// ---------------------------------------------------------------------------
// Col pass, ALL levels fused + weighted accumulate (includes b0*base) -> G
// ---------------------------------------------------------------------------
template <int S>
__device__ __forceinline__ void col_load(float4 (*sh)[F4], int lvl, int i, int j0,
                                         int f4, int tg)
{
    size_t lb = (size_t)lvl * NPIX * F4;
    for (int rr = tg; rr < 96; rr += 8) {
        int c = reflect_i(j0 - 16 + rr);
        sh[rr][f4] = g_tmp[lb + ((size_t)i * R + c) * F4 + f4];
    }
}

template <int S>
__device__ __forceinline__ void col_acc(const float4 (*sh)[F4], const KW& kw,
                                        float bl, int base, int f4, float4* acc)
{
    float kr[S];
#pragma unroll
    for (int n = 0; n < S; n++) kr[n] = bl * kw.w[S - 2 + n];
#pragma unroll
    for (int r = 0; r < 8 + S - 1; r++) {
        float4 v = sh[base + 16 - S / 2 + r][f4];
#pragma unroll
        for (int q = 0; q < 8; q++) {
            int jj = r - q;
            if (jj >= 0 && jj < S) {
                float k = kr[jj];
                acc[q].x += k * v.x; acc[q].y += k * v.y;
                acc[q].z += k * v.z; acc[q].w += k * v.w;
            }
        }
    }
}

__global__ void __launch_bounds__(256) k_cols(const float4* __restrict__ base4,
                                              const float* __restrict__ b_levels,
                                              KW kw)
{
    __shared__ float4 sh[96][F4];
    int i  = blockIdx.x;
    int j0 = blockIdx.y * 64;
    int t  = threadIdx.x;
    int f4 = t & 31, tg = t >> 5;
    int base = tg * 8;

    float b0 = b_levels[0];
    float4 acc[8];
#pragma unroll
    for (int q = 0; q < 8; q++) {
        float4 v = base4[((size_t)i * R + (j0 + base + q)) * F4 + f4];
        acc[q] = make_float4(b0 * v.x, b0 * v.y, b0 * v.z, b0 * v.w);
    }

    col_load<2 >(sh, 0, i, j0, f4, tg); __syncthreads();
    col_acc <2 >(sh, kw, b_levels[1], base, f4, acc); __syncthreads();
    col_load<4 >(sh, 1, i, j0, f4, tg); __syncthreads();
    col_acc <4 >(sh, kw, b_levels[2], base, f4, acc); __syncthreads();
    col_load<8 >(sh, 2, i, j0, f4, tg); __syncthreads();
    col_acc <8 >(sh, kw, b_levels[3], base, f4, acc); __syncthreads();
    col_load<16>(sh, 3, i, j0, f4, tg); __syncthreads();
    col_acc <16>(sh, kw, b_levels[4], base, f4, acc); __syncthreads();
    col_load<32>(sh, 4, i, j0, f4, tg); __syncthreads();
    col_acc <32>(sh, kw, b_levels[5], base, f4, acc);

#pragma unroll
    for (int q = 0; q < 8; q++)
        g_G[((size_t)i * R + (j0 + base + q)) * F4 + f4] = acc[q];
}

// ---------------------------------------------------------------------------
// H = G @ W1 + b1   (65536 x 128 @ 128 x 128), 128 rows per block.
// ---------------------------------------------------------------------------
#define SMEM_H (67584 * 2 + 512)

__global__ void __launch_bounds__(256, 1) k_H(const float* __restrict__ W1,
                                              const float* __restrict__ b1)
{
    extern __shared__ unsigned char smem_raw[];
    float4* A4   = (float4*)smem_raw;                    // 128 x 33 float4
    float4* w1t4 = (float4*)(smem_raw + 67584);          // 128 x 33 float4
    float*  b1s  = (float*) (smem_raw + 135168);         // 128 floats

    int t = threadIdx.x, blk = blockIdx.x;

    // W1^T into shared
#pragma unroll
    for (int it = 0; it < 16; it++) {
        int task = it * 256 + t;
        int f4 = task >> 7;
        int k  = task & 127;
        w1t4[k * 33 + f4] = make_float4(W1[(4 * f4 + 0) * 128 + k],
                                        W1[(4 * f4 + 1) * 128 + k],
                                        W1[(4 * f4 + 2) * 128 + k],
                                        W1[(4 * f4 + 3) * 128 + k]);
    }
    if (t < 128) b1s[t] = b1[t];

    // A tile (coalesced)
#pragma unroll
    for (int it = 0; it < 16; it++) {
        int task = it * 256 + t;
        int p  = task >> 5;
        int f4 = task & 31;
        A4[p * 33 + f4] = g_G[((size_t)blk * 128 + p) * F4 + f4];
    }
    __syncthreads();

    int li = t & 15;
    int lj = t >> 4;
    float acc[8][8];
#pragma unroll
    for (int q = 0; q < 8; q++)
#pragma unroll
        for (int r = 0; r < 8; r++) acc[q][r] = 0.0f;

#pragma unroll 4
    for (int f4 = 0; f4 < 32; f4++) {
        float4 a[8], bb[8];
#pragma unroll
        for (int q = 0; q < 8; q++) a[q] = A4[(li + 16 * q) * 33 + f4];
#pragma unroll
        for (int r = 0; r < 8; r++) bb[r] = w1t4[(lj + 16 * r) * 33 + f4];
#pragma unroll
        for (int q = 0; q < 8; q++)
#pragma unroll
            for (int r = 0; r < 8; r++) {
                acc[q][r] += a[q].x * bb[r].x;
                acc[q][r] += a[q].y * bb[r].y;
                acc[q][r] += a[q].z * bb[r].z;
                acc[q][r] += a[q].w * bb[r].w;
            }
    }

    float bias[8];
#pragma unroll
    for (int r = 0; r < 8; r++) bias[r] = b1s[lj + 16 * r];
    __syncthreads();   // everyone done reading A4 -> reuse as staging

    float* Hs = (float*)smem_raw;   // 128 x 132
#pragma unroll
    for (int q = 0; q < 8; q++)
#pragma unroll
        for (int r = 0; r < 8; r++)
            Hs[(li + 16 * q) * 132 + (lj + 16 * r)] = acc[q][r] + bias[r];
    __syncthreads();

    float* Hout = (float*)g_H;
#pragma unroll
    for (int it = 0; it < 64; it++) {
        int task = it * 256 + t;
        int p = task >> 7;
        int k = task & 127;
        Hout[((size_t)blk * 128 + p) * 128 + k] = Hs[p * 132 + k];
    }
}

// ---------------------------------------------------------------------------
// Points: bilerp gather of H (includes W1+b1 already) + relu + W2 + b2.
// Warp = 1 point per iter; lane = 1 float4 of features. 16 pts per warp.
// ---------------------------------------------------------------------------
__global__ void __launch_bounds__(256) k_pts(const float* __restrict__ pt,
                                             const float4* __restrict__ W2v,
                                             const float* __restrict__ b2,
                                             float4* __restrict__ out4)
{
    int t = threadIdx.x, lane = t & 31, w = t >> 5;

    // per-lane W2 rows: features 4*lane .. 4*lane+3, each row is float4 over outputs
    float4 w2r0 = W2v[4 * lane + 0];
    float4 w2r1 = W2v[4 * lane + 1];
    float4 w2r2 = W2v[4 * lane + 2];
    float4 w2r3 = W2v[4 * lane + 3];
    float b20 = b2[0], b21 = b2[1], b22 = b2[2], b23 = b2[3];

    int p0 = blockIdx.x * 128 + w * 16;
#pragma unroll 2
    for (int it = 0; it < 16; it++) {
        int p = p0 + it;
        float px = pt[2 * p];
        float py = pt[2 * p + 1];
        float ax = (px + 1.0f) / 2.0f * 255.0f;
        float ay = (py + 1.0f) / 2.0f * 255.0f;
        int ix = (int)ax; if (ix > 255) ix = 255;
        int iy = (int)ay; if (iy > 255) iy = 255;
        float fx = ax - (float)ix;
        float fy = ay - (float)iy;
        int ix1 = (ix + 1 > 255) ? 255 : ix + 1;
        int iy1 = (iy + 1 > 255) ? 255 : iy + 1;
        float w00 = (1.0f - fx) * (1.0f - fy);
        float w01 = (1.0f - fx) * fy;
        float w10 = fx * (1.0f - fy);
        float w11 = fx * fy;

        float4 c00 = g_H[((size_t)(ix  * R + iy )) * F4 + lane];
        float4 c01 = g_H[((size_t)(ix  * R + iy1)) * F4 + lane];
        float4 c10 = g_H[((size_t)(ix1 * R + iy )) * F4 + lane];
        float4 c11 = g_H[((size_t)(ix1 * R + iy1)) * F4 + lane];

        float4 v;
        v.x = w00 * c00.x + w01 * c01.x + w10 * c10.x + w11 * c11.x;
        v.y = w00 * c00.y + w01 * c01.y + w10 * c10.y + w11 * c11.y;
        v.z = w00 * c00.z + w01 * c01.z + w10 * c10.z + w11 * c11.z;
        v.w = w00 * c00.w + w01 * c01.w + w10 * c10.w + w11 * c11.w;
        v.x = fmaxf(v.x, 0.0f); v.y = fmaxf(v.y, 0.0f);
        v.z = fmaxf(v.z, 0.0f); v.w = fmaxf(v.w, 0.0f);

        float4 o;
        o.x = v.x * w2r0.x + v.y * w2r1.x + v.z * w2r2.x + v.w * w2r3.x;
        o.y = v.x * w2r0.y + v.y * w2r1.y + v.z * w2r2.y + v.w * w2r3.y;
        o.z = v.x * w2r0.z + v.y * w2r1.z + v.z * w2r2.z + v.w * w2r3.z;
        o.w = v.x * w2r0.w + v.y * w2r1.w + v.z * w2r2.w + v.w * w2r3.w;

#pragma unroll
        for (int off = 16; off; off >>= 1) {
            o.x += __shfl_xor_sync(0xffffffffu, o.x, off);
            o.y += __shfl_xor_sync(0xffffffffu, o.y, off);
            o.z += __shfl_xor_sync(0xffffffffu, o.z, off);
            o.w += __shfl_xor_sync(0xffffffffu, o.w, off);
        }
        if (lane == 0)
            out4[p] = make_float4(o.x + b20, o.y + b21, o.z + b22, o.w + b23);
    }
}

// ---------------------------------------------------------------------------
static void fill_kw(KW& kw)
{
    for (int l = 1; l <= 5; l++) {
        int s = 1 << l;
        int off = s - 2;
        double stdv = s * 0.5;
        double tmp[32];
        double sum = 0.0;
        for (int n = 0; n < s; n++) {
            double x = ((double)n - (s - 1) * 0.5) / stdv;
            tmp[n] = exp(-0.5 * x * x);
            sum += tmp[n];
        }
        for (int n = 0; n < s; n++) kw.w[off + n] = (float)(tmp[n] / sum);
    }
}

extern "C" void kernel_launch(void* const* d_in, const int* in_sizes, int n_in,
                              void* d_out, int out_size) {
    const float*  pt       = (const float*)d_in[0];
    const float4* base4    = (const float4*)d_in[1];
    const float*  b_levels = (const float*)d_in[2];
    const float*  W1       = (const float*)d_in[3];
    const float*  b1       = (const float*)d_in[4];
    const float*  W2       = (const float*)d_in[5];
    const float*  b2       = (const float*)d_in[6];
    float* out             = (float*)d_out;

    KW kw;
    fill_kw(kw);

    cudaFuncSetAttribute(k_H, cudaFuncAttributeMaxDynamicSharedMemorySize, SMEM_H);

    dim3 bg(256, 4);
    k_rows<<<bg, 256>>>(base4, kw);
    k_cols<<<bg, 256>>>(base4, b_levels, kw);
    k_H<<<512, 256, SMEM_H>>>(W1, b1);
    k_pts<<<2048, 256>>>(pt, (const float4*)W2, b2, (float4*)out);
}

// round 3
// speedup vs baseline: 2.3391x; 1.4045x over previous
#include <cuda_runtime.h>
#include <cuda_fp16.h>
#include <math.h>

#define R 256
#define F4 32           // 128 features = 32 float4
#define NPIX (R * R)

// Static device scratch
__device__ uint2  g_tmph[5 * (size_t)NPIX * F4];  // row-blurred levels, fp16x4 (84 MB)
__device__ float4 g_H[NPIX * F4];                 // H = G @ W1 + b1 (33.5 MB)

struct KW { float w[62]; };   // gaussian windows, offset s-2

__device__ __forceinline__ int reflect_i(int c) {
    c = (c < 0) ? -c : c;
    return (c > R - 1) ? (2 * (R - 1) - c) : c;
}

__device__ __forceinline__ uint2 pack4(float4 v) {
    __half2 a = __floats2half2_rn(v.x, v.y);
    __half2 b = __floats2half2_rn(v.z, v.w);
    uint2 r;
    r.x = *reinterpret_cast<unsigned*>(&a);
    r.y = *reinterpret_cast<unsigned*>(&b);
    return r;
}

__device__ __forceinline__ float4 unpack4(uint2 u) {
    __half2 a = *reinterpret_cast<__half2*>(&u.x);
    __half2 b = *reinterpret_cast<__half2*>(&u.y);
    float2 fa = __half22float2(a);
    float2 fb = __half22float2(b);
    return make_float4(fa.x, fa.y, fb.x, fb.y);
}

// ---------------------------------------------------------------------------
// Row pass, all 5 levels fused: load 96-row tile once, emit 5 levels (fp16).
// ---------------------------------------------------------------------------
template <int S>
__device__ __forceinline__ void row_level(const float4 (*sh)[F4], const KW& kw,
                                          int base, int f4, int lvl, int i0, int j)
{
    float4 acc[8];
#pragma unroll
    for (int q = 0; q < 8; q++) acc[q] = make_float4(0.f, 0.f, 0.f, 0.f);
#pragma unroll
    for (int r = 0; r < 8 + S - 1; r++) {
        float4 v = sh[base + 16 - S / 2 + r][f4];
#pragma unroll
        for (int q = 0; q < 8; q++) {
            int jj = r - q;
            if (jj >= 0 && jj < S) {
                float k = kw.w[S - 2 + jj];
                acc[q].x += k * v.x; acc[q].y += k * v.y;
                acc[q].z += k * v.z; acc[q].w += k * v.w;
            }
        }
    }
    size_t lb = (size_t)lvl * NPIX * F4;
#pragma unroll
    for (int q = 0; q < 8; q++)
        g_tmph[lb + ((size_t)(i0 + base + q) * R + j) * F4 + f4] = pack4(acc[q]);
}

__global__ void __launch_bounds__(256) k_rows(const float4* __restrict__ in, KW kw)
{
    __shared__ float4 sh[96][F4];
    int j  = blockIdx.x;
    int i0 = blockIdx.y * 64;
    int t  = threadIdx.x;
    int f4 = t & 31, tg = t >> 5;

    for (int rr = tg; rr < 96; rr += 8) {
        int c = reflect_i(i0 - 16 + rr);
        sh[rr][f4] = in[((size_t)c * R + j) * F4 + f4];
    }
    __syncthreads();

    int base = tg * 8;
    row_level<2 >(sh, kw, base, f4, 0, i0, j);
    row_level<4 >(sh, kw, base, f4, 1, i0, j);
    row_level<8 >(sh, kw, base, f4, 2, i0, j);
    row_level<16>(sh, kw, base, f4, 3, i0, j);
    row_level<32>(sh, kw, base, f4, 4, i0, j);
}

// ---------------------------------------------------------------------------
// Col pass (all levels, weighted accumulate incl. b0*base) FUSED with
// H = G @ W1 + b1. One block = one row i, 64 columns, all 128 features.
// Dynamic smem layout:
//   sh    : float4[96][32]   49152 B   (tile staging; reused as Hs)
//   w1t4  : float4[128*33]   67584 B   @ 49152
//   Gs    : float4[64*33]    33792 B   @ 116736
//   b1s   : float[128]         512 B   @ 150528
// total 151040 B
// ---------------------------------------------------------------------------
#define SMEM_CH 151040

template <int S>
__device__ __forceinline__ void col_load(float4 (*sh)[F4], int lvl, int i, int j0,
                                         int f4, int tg)
{
    size_t lb = (size_t)lvl * NPIX * F4;
#pragma unroll
    for (int rr = tg; rr < 96; rr += 8) {
        int c = reflect_i(j0 - 16 + rr);
        sh[rr][f4] = unpack4(g_tmph[lb + ((size_t)i * R + c) * F4 + f4]);
    }
}

template <int S>
__device__ __forceinline__ void col_acc(const float4 (*sh)[F4], const KW& kw,
                                        float bl, int base, int f4, float4* acc)
{
    float kr[S];
#pragma unroll
    for (int n = 0; n < S; n++) kr[n] = bl * kw.w[S - 2 + n];
#pragma unroll
    for (int r = 0; r < 8 + S - 1; r++) {
        float4 v = sh[base + 16 - S / 2 + r][f4];
#pragma unroll
        for (int q = 0; q < 8; q++) {
            int jj = r - q;
            if (jj >= 0 && jj < S) {
                float k = kr[jj];
                acc[q].x += k * v.x; acc[q].y += k * v.y;
                acc[q].z += k * v.z; acc[q].w += k * v.w;
            }
        }
    }
}

__global__ void __launch_bounds__(256, 1) k_colsH(const float4* __restrict__ base4,
                                                  const float* __restrict__ b_levels,
                                                  const float* __restrict__ W1,
                                                  const float* __restrict__ b1,
                                                  KW kw)
{
    extern __shared__ unsigned char smem_raw[];
    float4 (*sh)[F4] = (float4 (*)[F4])smem_raw;
    float4* w1t4 = (float4*)(smem_raw + 49152);
    float4* Gs   = (float4*)(smem_raw + 116736);
    float*  b1s  = (float*) (smem_raw + 150528);

    int i  = blockIdx.x;
    int j0 = blockIdx.y * 64;
    int t  = threadIdx.x;
    int f4 = t & 31, tg = t >> 5;
    int base = tg * 8;

    // W1^T + b1 into shared (done once, overlapped with first tile load)
#pragma unroll
    for (int it = 0; it < 16; it++) {
        int task = it * 256 + t;
        int ff = task >> 7;
        int k  = task & 127;
        w1t4[k * 33 + ff] = make_float4(W1[(4 * ff + 0) * 128 + k],
                                        W1[(4 * ff + 1) * 128 + k],
                                        W1[(4 * ff + 2) * 128 + k],
                                        W1[(4 * ff + 3) * 128 + k]);
    }
    if (t < 128) b1s[t] = b1[t];

    float b0 = b_levels[0];
    float4 acc[8];
#pragma unroll
    for (int q = 0; q < 8; q++) {
        float4 v = base4[((size_t)i * R + (j0 + base + q)) * F4 + f4];
        acc[q] = make_float4(b0 * v.x, b0 * v.y, b0 * v.z, b0 * v.w);
    }

    col_load<2 >(sh, 0, i, j0, f4, tg); __syncthreads();
    col_acc <2 >(sh, kw, b_levels[1], base, f4, acc); __syncthreads();
    col_load<4 >(sh, 1, i, j0, f4, tg); __syncthreads();
    col_acc <4 >(sh, kw, b_levels[2], base, f4, acc); __syncthreads();
    col_load<8 >(sh, 2, i, j0, f4, tg); __syncthreads();
    col_acc <8 >(sh, kw, b_levels[3], base, f4, acc); __syncthreads();
    col_load<16>(sh, 3, i, j0, f4, tg); __syncthreads();
    col_acc <16>(sh, kw, b_levels[4], base, f4, acc); __syncthreads();
    col_load<32>(sh, 4, i, j0, f4, tg); __syncthreads();
    col_acc <32>(sh, kw, b_levels[5], base, f4, acc);

    // Stage G tile: Gs[p][f4], p = local pixel (column offset)
#pragma unroll
    for (int q = 0; q < 8; q++)
        Gs[(base + q) * 33 + f4] = acc[q];
    __syncthreads();

    // GEMM: 64 pixels x 128 outputs. thread: 4 pixels x 8 k's.
    int pi = t & 15;       // pixels pi + 16u
    int kj = t >> 4;       // ks     kj + 16r
    float acc2[4][8];
#pragma unroll
    for (int u = 0; u < 4; u++)
#pragma unroll
        for (int r = 0; r < 8; r++) acc2[u][r] = 0.0f;

#pragma unroll 4
    for (int ff = 0; ff < 32; ff++) {
        float4 a[4], bb[8];
#pragma unroll
        for (int u = 0; u < 4; u++) a[u] = Gs[(pi + 16 * u) * 33 + ff];
#pragma unroll
        for (int r = 0; r < 8; r++) bb[r] = w1t4[(kj + 16 * r) * 33 + ff];
#pragma unroll
        for (int u = 0; u < 4; u++)
#pragma unroll
            for (int r = 0; r < 8; r++) {
                acc2[u][r] += a[u].x * bb[r].x;
                acc2[u][r] += a[u].y * bb[r].y;
                acc2[u][r] += a[u].z * bb[r].z;
                acc2[u][r] += a[u].w * bb[r].w;
            }
    }
    __syncthreads();   // done reading sh -> reuse as Hs

    float* Hs = (float*)smem_raw;   // 64 x 132
#pragma unroll
    for (int u = 0; u < 4; u++)
#pragma unroll
        for (int r = 0; r < 8; r++)
            Hs[(pi + 16 * u) * 132 + (kj + 16 * r)] = acc2[u][r] + b1s[kj + 16 * r];
    __syncthreads();

    float4* Hs4 = (float4*)Hs;
#pragma unroll
    for (int it = 0; it < 8; it++) {
        int task = it * 256 + t;
        int p  = task >> 5;
        int k4 = task & 31;
        g_H[((size_t)(i * R + j0 + p)) * F4 + k4] = Hs4[p * 33 + k4];
    }
}

// ---------------------------------------------------------------------------
// Points: bilerp gather of H + relu + W2 + b2.
// ---------------------------------------------------------------------------
__global__ void __launch_bounds__(256) k_pts(const float* __restrict__ pt,
                                             const float4* __restrict__ W2v,
                                             const float* __restrict__ b2,
                                             float4* __restrict__ out4)
{
    int t = threadIdx.x, lane = t & 31, w = t >> 5;

    float4 w2r0 = W2v[4 * lane + 0];
    float4 w2r1 = W2v[4 * lane + 1];
    float4 w2r2 = W2v[4 * lane + 2];
    float4 w2r3 = W2v[4 * lane + 3];
    float b20 = b2[0], b21 = b2[1], b22 = b2[2], b23 = b2[3];

    int p0 = blockIdx.x * 128 + w * 16;
#pragma unroll 2
    for (int it = 0; it < 16; it++) {
        int p = p0 + it;
        float px = pt[2 * p];
        float py = pt[2 * p + 1];
        float ax = (px + 1.0f) / 2.0f * 255.0f;
        float ay = (py + 1.0f) / 2.0f * 255.0f;
        int ix = (int)ax; if (ix > 255) ix = 255;
        int iy = (int)ay; if (iy > 255) iy = 255;
        float fx = ax - (float)ix;
        float fy = ay - (float)iy;
        int ix1 = (ix + 1 > 255) ? 255 : ix + 1;
        int iy1 = (iy + 1 > 255) ? 255 : iy + 1;
        float w00 = (1.0f - fx) * (1.0f - fy);
        float w01 = (1.0f - fx) * fy;
        float w10 = fx * (1.0f - fy);
        float w11 = fx * fy;

        float4 c00 = g_H[((size_t)(ix  * R + iy )) * F4 + lane];
        float4 c01 = g_H[((size_t)(ix  * R + iy1)) * F4 + lane];
        float4 c10 = g_H[((size_t)(ix1 * R + iy )) * F4 + lane];
        float4 c11 = g_H[((size_t)(ix1 * R + iy1)) * F4 + lane];

        float4 v;
        v.x = w00 * c00.x + w01 * c01.x + w10 * c10.x + w11 * c11.x;
        v.y = w00 * c00.y + w01 * c01.y + w10 * c10.y + w11 * c11.y;
        v.z = w00 * c00.z + w01 * c01.z + w10 * c10.z + w11 * c11.z;
        v.w = w00 * c00.w + w01 * c01.w + w10 * c10.w + w11 * c11.w;
        v.x = fmaxf(v.x, 0.0f); v.y = fmaxf(v.y, 0.0f);
        v.z = fmaxf(v.z, 0.0f); v.w = fmaxf(v.w, 0.0f);

        float4 o;
        o.x = v.x * w2r0.x + v.y * w2r1.x + v.z * w2r2.x + v.w * w2r3.x;
        o.y = v.x * w2r0.y + v.y * w2r1.y + v.z * w2r2.y + v.w * w2r3.y;
        o.z = v.x * w2r0.z + v.y * w2r1.z + v.z * w2r2.z + v.w * w2r3.z;
        o.w = v.x * w2r0.w + v.y * w2r1.w + v.z * w2r2.w + v.w * w2r3.w;

#pragma unroll
        for (int off = 16; off; off >>= 1) {
            o.x += __shfl_xor_sync(0xffffffffu, o.x, off);
            o.y += __shfl_xor_sync(0xffffffffu, o.y, off);
            o.z += __shfl_xor_sync(0xffffffffu, o.z, off);
            o.w += __shfl_xor_sync(0xffffffffu, o.w, off);
        }
        if (lane == 0)
            out4[p] = make_float4(o.x + b20, o.y + b21, o.z + b22, o.w + b23);
    }
}

// ---------------------------------------------------------------------------
static void fill_kw(KW& kw)
{
    for (int l = 1; l <= 5; l++) {
        int s = 1 << l;
        int off = s - 2;
        double stdv = s * 0.5;
        double tmp[32];
        double sum = 0.0;
        for (int n = 0; n < s; n++) {
            double x = ((double)n - (s - 1) * 0.5) / stdv;
            tmp[n] = exp(-0.5 * x * x);
            sum += tmp[n];
        }
        for (int n = 0; n < s; n++) kw.w[off + n] = (float)(tmp[n] / sum);
    }
}

extern "C" void kernel_launch(void* const* d_in, const int* in_sizes, int n_in,
                              void* d_out, int out_size) {
    const float*  pt       = (const float*)d_in[0];
    const float4* base4    = (const float4*)d_in[1];
    const float*  b_levels = (const float*)d_in[2];
    const float*  W1       = (const float*)d_in[3];
    const float*  b1       = (const float*)d_in[4];
    const float*  W2       = (const float*)d_in[5];
    const float*  b2       = (const float*)d_in[6];
    float* out             = (float*)d_out;

    KW kw;
    fill_kw(kw);

    cudaFuncSetAttribute(k_colsH, cudaFuncAttributeMaxDynamicSharedMemorySize,
                         SMEM_CH);

    dim3 bg(256, 4);
    k_rows<<<bg, 256>>>(base4, kw);
    k_colsH<<<bg, 256, SMEM_CH>>>(base4, b_levels, W1, b1, kw);
    k_pts<<<2048, 256>>>(pt, (const float4*)W2, b2, (float4*)out);
}

// round 4
// speedup vs baseline: 2.9493x; 1.2609x over previous
#include <cuda_runtime.h>
#include <cuda_fp16.h>
#include <math.h>

#define R 256
#define F4 32           // 128 features = 32 float4
#define NPIX (R * R)

// Static device scratch
__device__ uint2 g_tmph[5 * (size_t)NPIX * F4];  // row-blurred levels, fp16x4 (84 MB)
__device__ uint4 g_Hh[(size_t)NPIX * 16];        // H = G@W1+b1, fp16 (16.8 MB)

struct KW { float w[62]; };   // gaussian windows, offset s-2

__device__ __forceinline__ int reflect_i(int c) {
    c = (c < 0) ? -c : c;
    return (c > R - 1) ? (2 * (R - 1) - c) : c;
}

__device__ __forceinline__ uint2 pack4(float4 v) {
    __half2 a = __floats2half2_rn(v.x, v.y);
    __half2 b = __floats2half2_rn(v.z, v.w);
    uint2 r;
    r.x = *reinterpret_cast<unsigned*>(&a);
    r.y = *reinterpret_cast<unsigned*>(&b);
    return r;
}

__device__ __forceinline__ float4 unpack4(uint2 u) {
    __half2 a = *reinterpret_cast<__half2*>(&u.x);
    __half2 b = *reinterpret_cast<__half2*>(&u.y);
    float2 fa = __half22float2(a);
    float2 fb = __half22float2(b);
    return make_float4(fa.x, fa.y, fb.x, fb.y);
}

__device__ __forceinline__ unsigned f2tf32(float f) {
    unsigned u;
    asm("cvt.rna.tf32.f32 %0, %1;" : "=r"(u) : "f"(f));
    return u;
}

__device__ __forceinline__ void mma_tf32(float* d, unsigned a0, unsigned a1,
                                         unsigned a2, unsigned a3,
                                         unsigned b0, unsigned b1) {
    asm("mma.sync.aligned.m16n8k8.row.col.f32.tf32.tf32.f32 "
        "{%0,%1,%2,%3},{%4,%5,%6,%7},{%8,%9},{%0,%1,%2,%3};"
        : "+f"(d[0]), "+f"(d[1]), "+f"(d[2]), "+f"(d[3])
        : "r"(a0), "r"(a1), "r"(a2), "r"(a3), "r"(b0), "r"(b1));
}

// ---------------------------------------------------------------------------
// Row pass, all 5 levels fused. 512 threads, 4 rows per thread.
// ---------------------------------------------------------------------------
template <int S>
__device__ __forceinline__ void row_level(const float4 (*sh)[F4], const KW& kw,
                                          int base, int f4, int lvl, int i0, int j)
{
    float4 acc[4];
#pragma unroll
    for (int q = 0; q < 4; q++) acc[q] = make_float4(0.f, 0.f, 0.f, 0.f);
#pragma unroll
    for (int r = 0; r < 4 + S - 1; r++) {
        float4 v = sh[base + 16 - S / 2 + r][f4];
#pragma unroll
        for (int q = 0; q < 4; q++) {
            int jj = r - q;
            if (jj >= 0 && jj < S) {
                float k = kw.w[S - 2 + jj];
                acc[q].x += k * v.x; acc[q].y += k * v.y;
                acc[q].z += k * v.z; acc[q].w += k * v.w;
            }
        }
    }
    size_t lb = (size_t)lvl * NPIX * F4;
#pragma unroll
    for (int q = 0; q < 4; q++)
        g_tmph[lb + ((size_t)(i0 + base + q) * R + j) * F4 + f4] = pack4(acc[q]);
}

__global__ void __launch_bounds__(512, 2) k_rows(const float4* __restrict__ in, KW kw)
{
    __shared__ float4 sh[96][F4];
    int j  = blockIdx.x;
    int i0 = blockIdx.y * 64;
    int t  = threadIdx.x;
    int f4 = t & 31, tg = t >> 5;           // tg 0..15

    for (int rr = tg; rr < 96; rr += 16) {
        int c = reflect_i(i0 - 16 + rr);
        sh[rr][f4] = in[((size_t)c * R + j) * F4 + f4];
    }
    __syncthreads();

    int base = tg * 4;
    row_level<2 >(sh, kw, base, f4, 0, i0, j);
    row_level<4 >(sh, kw, base, f4, 1, i0, j);
    row_level<8 >(sh, kw, base, f4, 2, i0, j);
    row_level<16>(sh, kw, base, f4, 3, i0, j);
    row_level<32>(sh, kw, base, f4, 4, i0, j);
}

// ---------------------------------------------------------------------------
// Col pass (all levels + b0*base) FUSED with H = G @ W1 + b1 via tf32 MMA.
// One block = one row i, 64 columns, 256 threads (8 warps).
// smem layout (bytes):
//   sh   : float4[96][32]       49152 @ 0       (blur staging; reused as Hs fp16)
//   W1p  : uint2[64*132]        67584 @ 49152   (tf32 pairs (k, k+4), stride 132)
//   Gs   : uint[64*132]         33792 @ 116736  (tf32 G tile, stride 132)
//   b1s  : float[128]             512 @ 150528
// total 151040
// ---------------------------------------------------------------------------
#define SMEM_CH 151040

template <int S>
__device__ __forceinline__ void col_load(float4 (*sh)[F4], int lvl, int i, int j0,
                                         int f4, int tg)
{
    size_t lb = (size_t)lvl * NPIX * F4;
#pragma unroll
    for (int rr = tg; rr < 96; rr += 8) {
        int c = reflect_i(j0 - 16 + rr);
        sh[rr][f4] = unpack4(g_tmph[lb + ((size_t)i * R + c) * F4 + f4]);
    }
}

template <int S>
__device__ __forceinline__ void col_acc(const float4 (*sh)[F4], const KW& kw,
                                        float bl, int base, int f4, float4* acc)
{
    float kr[S];
#pragma unroll
    for (int n = 0; n < S; n++) kr[n] = bl * kw.w[S - 2 + n];
#pragma unroll
    for (int r = 0; r < 8 + S - 1; r++) {
        float4 v = sh[base + 16 - S / 2 + r][f4];
#pragma unroll
        for (int q = 0; q < 8; q++) {
            int jj = r - q;
            if (jj >= 0 && jj < S) {
                float k = kr[jj];
                acc[q].x += k * v.x; acc[q].y += k * v.y;
                acc[q].z += k * v.z; acc[q].w += k * v.w;
            }
        }
    }
}

__global__ void __launch_bounds__(256, 1) k_colsH(const float4* __restrict__ base4,
                                                  const float* __restrict__ b_levels,
                                                  const float* __restrict__ W1,
                                                  const float* __restrict__ b1,
                                                  KW kw)
{
    extern __shared__ unsigned char smem_raw[];
    float4 (*sh)[F4]   = (float4 (*)[F4])smem_raw;
    uint2*    W1p      = (uint2*)(smem_raw + 49152);
    unsigned* Gs       = (unsigned*)(smem_raw + 116736);
    float*    b1s      = (float*)(smem_raw + 150528);

    int i  = blockIdx.x;
    int j0 = blockIdx.y * 64;
    int t  = threadIdx.x;
    int f4 = t & 31, tg = t >> 5;
    int base = tg * 8;

    // W1 pairs (k, k+4) -> tf32 uint2, plus b1. Coalesced global reads.
#pragma unroll
    for (int it = 0; it < 32; it++) {
        int task = it * 256 + t;
        int r = task >> 7;          // 0..63 : pack-row
        int n = task & 127;
        int klo = 8 * (r >> 2) + (r & 3);
        uint2 v;
        v.x = f2tf32(W1[klo * 128 + n]);
        v.y = f2tf32(W1[(klo + 4) * 128 + n]);
        W1p[r * 132 + n] = v;
    }
    if (t < 128) b1s[t] = b1[t];

    float b0 = b_levels[0];
    float4 acc[8];
#pragma unroll
    for (int q = 0; q < 8; q++) {
        float4 v = base4[((size_t)i * R + (j0 + base + q)) * F4 + f4];
        acc[q] = make_float4(b0 * v.x, b0 * v.y, b0 * v.z, b0 * v.w);
    }

    col_load<2 >(sh, 0, i, j0, f4, tg); __syncthreads();
    col_acc <2 >(sh, kw, b_levels[1], base, f4, acc); __syncthreads();
    col_load<4 >(sh, 1, i, j0, f4, tg); __syncthreads();
    col_acc <4 >(sh, kw, b_levels[2], base, f4, acc); __syncthreads();
    col_load<8 >(sh, 2, i, j0, f4, tg); __syncthreads();
    col_acc <8 >(sh, kw, b_levels[3], base, f4, acc); __syncthreads();
    col_load<16>(sh, 3, i, j0, f4, tg); __syncthreads();
    col_acc <16>(sh, kw, b_levels[4], base, f4, acc); __syncthreads();
    col_load<32>(sh, 4, i, j0, f4, tg); __syncthreads();
    col_acc <32>(sh, kw, b_levels[5], base, f4, acc);

    // Stage G tile as tf32 (uint4 vector stores; (row*132 + 4*f4) is 16B aligned)
#pragma unroll
    for (int q = 0; q < 8; q++) {
        uint4 u;
        u.x = f2tf32(acc[q].x); u.y = f2tf32(acc[q].y);
        u.z = f2tf32(acc[q].z); u.w = f2tf32(acc[q].w);
        *reinterpret_cast<uint4*>(&Gs[(base + q) * 132 + 4 * f4]) = u;
    }
    __syncthreads();

    // MMA: 64 x 128 = (4 m-tiles of 16) x (2 n-halves of 64). warp = (mt, nh).
    int w    = t >> 5;
    int lane = t & 31;
    int mt   = w & 3;
    int nh   = w >> 2;
    int g    = lane >> 2;
    int tig  = lane & 3;

    float d[8][4];
#pragma unroll
    for (int nt = 0; nt < 8; nt++)
#pragma unroll
        for (int e = 0; e < 4; e++) d[nt][e] = 0.0f;

#pragma unroll 4
    for (int kk = 0; kk < 16; kk++) {
        int arow = (mt * 16 + g) * 132 + kk * 8 + tig;
        unsigned a0 = Gs[arow];
        unsigned a1 = Gs[arow + 8 * 132];
        unsigned a2 = Gs[arow + 4];
        unsigned a3 = Gs[arow + 8 * 132 + 4];
        int brow = (kk * 4 + tig) * 132 + nh * 64 + g;
#pragma unroll
        for (int nt = 0; nt < 8; nt++) {
            uint2 b = W1p[brow + nt * 8];
            mma_tf32(d[nt], a0, a1, a2, a3, b.x, b.y);
        }
    }

    // Epilogue: +b1, fp16 pack into Hs (reuse sh region; 64 x 68 half2)
    __half2* Hs2 = (__half2*)smem_raw;
    int m0 = mt * 16 + g;
#pragma unroll
    for (int nt = 0; nt < 8; nt++) {
        int n0 = nh * 64 + nt * 8 + 2 * tig;
        float bb0 = b1s[n0], bb1 = b1s[n0 + 1];
        Hs2[m0 * 68 + (n0 >> 1)]       = __floats2half2_rn(d[nt][0] + bb0, d[nt][1] + bb1);
        Hs2[(m0 + 8) * 68 + (n0 >> 1)] = __floats2half2_rn(d[nt][2] + bb0, d[nt][3] + bb1);
    }
    __syncthreads();

    // Coalesced fp16 store: 64 pixels x 16 uint4
    const uint4* Hs4 = (const uint4*)smem_raw;
#pragma unroll
    for (int it = 0; it < 4; it++) {
        int task = it * 256 + t;
        int p  = task >> 4;
        int q4 = task & 15;
        g_Hh[((size_t)(i * R + j0 + p)) * 16 + q4] = Hs4[p * 17 + q4];
    }
}

// ---------------------------------------------------------------------------
// Points: bilerp gather of fp16 H + relu + W2 + b2.
// Warp handles 2 points at once: lane = (pt-half lh, feature-group lf of 8).
// ---------------------------------------------------------------------------
__global__ void __launch_bounds__(256) k_pts(const float* __restrict__ pt,
                                             const float4* __restrict__ W2v,
                                             const float* __restrict__ b2,
                                             float4* __restrict__ out4)
{
    int t = threadIdx.x, lane = t & 31, w = t >> 5;
    int lh = lane >> 4;      // which of the 2 points
    int lf = lane & 15;      // feature group: feats 8*lf .. 8*lf+7

    float4 w2r[8];
#pragma unroll
    for (int j = 0; j < 8; j++) w2r[j] = W2v[lf * 8 + j];
    float b20 = b2[0], b21 = b2[1], b22 = b2[2], b23 = b2[3];

    int p0 = blockIdx.x * 128 + w * 16 + lh;
#pragma unroll 2
    for (int it = 0; it < 8; it++) {
        int p = p0 + it * 2;
        float px = pt[2 * p];
        float py = pt[2 * p + 1];
        float ax = (px + 1.0f) / 2.0f * 255.0f;
        float ay = (py + 1.0f) / 2.0f * 255.0f;
        int ix = (int)ax; if (ix > 255) ix = 255;
        int iy = (int)ay; if (iy > 255) iy = 255;
        float fx = ax - (float)ix;
        float fy = ay - (float)iy;
        int ix1 = (ix + 1 > 255) ? 255 : ix + 1;
        int iy1 = (iy + 1 > 255) ? 255 : iy + 1;
        float w00 = (1.0f - fx) * (1.0f - fy);
        float w01 = (1.0f - fx) * fy;
        float w10 = fx * (1.0f - fy);
        float w11 = fx * fy;

        uint4 c00 = g_Hh[((size_t)(ix  * R + iy )) * 16 + lf];
        uint4 c01 = g_Hh[((size_t)(ix  * R + iy1)) * 16 + lf];
        uint4 c10 = g_Hh[((size_t)(ix1 * R + iy )) * 16 + lf];
        uint4 c11 = g_Hh[((size_t)(ix1 * R + iy1)) * 16 + lf];

        float v[8];
#pragma unroll
        for (int k = 0; k < 8; k++) v[k] = 0.0f;
        {
            const unsigned* cs[4] = {&c00.x, &c01.x, &c10.x, &c11.x};
            float ws[4] = {w00, w01, w10, w11};
#pragma unroll
            for (int cc = 0; cc < 4; cc++) {
                float wgt = ws[cc];
#pragma unroll
                for (int k = 0; k < 4; k++) {
                    __half2 h = *reinterpret_cast<const __half2*>(&cs[cc][k]);
                    float2 f = __half22float2(h);
                    v[2 * k]     += wgt * f.x;
                    v[2 * k + 1] += wgt * f.y;
                }
            }
        }

        float4 o = make_float4(0.f, 0.f, 0.f, 0.f);
#pragma unroll
        for (int j = 0; j < 8; j++) {
            float h = fmaxf(v[j], 0.0f);
            o.x += h * w2r[j].x; o.y += h * w2r[j].y;
            o.z += h * w2r[j].z; o.w += h * w2r[j].w;
        }

#pragma unroll
        for (int off = 8; off; off >>= 1) {
            o.x += __shfl_xor_sync(0xffffffffu, o.x, off);
            o.y += __shfl_xor_sync(0xffffffffu, o.y, off);
            o.z += __shfl_xor_sync(0xffffffffu, o.z, off);
            o.w += __shfl_xor_sync(0xffffffffu, o.w, off);
        }
        if (lf == 0)
            out4[p] = make_float4(o.x + b20, o.y + b21, o.z + b22, o.w + b23);
    }
}

// ---------------------------------------------------------------------------
static void fill_kw(KW& kw)
{
    for (int l = 1; l <= 5; l++) {
        int s = 1 << l;
        int off = s - 2;
        double stdv = s * 0.5;
        double tmp[32];
        double sum = 0.0;
        for (int n = 0; n < s; n++) {
            double x = ((double)n - (s - 1) * 0.5) / stdv;
            tmp[n] = exp(-0.5 * x * x);
            sum += tmp[n];
        }
        for (int n = 0; n < s; n++) kw.w[off + n] = (float)(tmp[n] / sum);
    }
}

extern "C" void kernel_launch(void* const* d_in, const int* in_sizes, int n_in,
                              void* d_out, int out_size) {
    const float*  pt       = (const float*)d_in[0];
    const float4* base4    = (const float4*)d_in[1];
    const float*  b_levels = (const float*)d_in[2];
    const float*  W1       = (const float*)d_in[3];
    const float*  b1       = (const float*)d_in[4];
    const float*  W2       = (const float*)d_in[5];
    const float*  b2       = (const float*)d_in[6];
    float* out             = (float*)d_out;

    KW kw;
    fill_kw(kw);

    cudaFuncSetAttribute(k_colsH, cudaFuncAttributeMaxDynamicSharedMemorySize,
                         SMEM_CH);

    dim3 bg(256, 4);
    k_rows<<<bg, 512>>>(base4, kw);
    k_colsH<<<bg, 256, SMEM_CH>>>(base4, b_levels, W1, b1, kw);
    k_pts<<<2048, 256>>>(pt, (const float4*)W2, b2, (float4*)out);
}